// round 6
// baseline (speedup 1.0000x reference)
#include <cuda_runtime.h>
#include <cstdint>

#define BATCH   256
#define DIN     5120
#define RNK     160
#define NST     16
#define NOUT    192   // 160 (dt_low) + 16 (Bp) + 16 (C)
#define KSPLIT  64

// Scratch
__device__ float g_Part[KSPLIT * BATCH * NOUT]; // split-K partials [ks][b][j]
__device__ float g_Pt[NOUT * BATCH];            // P^T [out][batch]
__device__ float g_dt[BATCH * DIN];             // softplus'd delta [b][d]
__device__ float g_As2[DIN * NST];              // -exp(A_log)*log2e
__device__ float g_Ct[BATCH * NST];             // C transposed [b][n]
__device__ float g_SBC[BATCH];                  // sum_n Bp*C per batch

// ---------- f32x2 helpers ----------
__device__ __forceinline__ unsigned long long pack2(float lo, float hi) {
    unsigned long long r;
    asm("mov.b64 %0, {%1, %2};" : "=l"(r)
        : "r"(__float_as_uint(lo)), "r"(__float_as_uint(hi)));
    return r;
}
__device__ __forceinline__ void unpack2(unsigned long long v, float& lo, float& hi) {
    unsigned int a, b;
    asm("mov.b64 {%0, %1}, %2;" : "=r"(a), "=r"(b) : "l"(v));
    lo = __uint_as_float(a);
    hi = __uint_as_float(b);
}
__device__ __forceinline__ void ffma2(unsigned long long& d,
                                      unsigned long long a,
                                      unsigned long long b) {
    asm("fma.rn.f32x2 %0, %1, %2, %0;" : "+l"(d) : "l"(a), "l"(b));
}
__device__ __forceinline__ float ex2f(float x) {
    float r;
    asm("ex2.approx.ftz.f32 %0, %1;" : "=f"(r) : "f"(x));
    return r;
}
__device__ __forceinline__ float softplus20(float z) {
    return (z > 20.0f) ? z : fmaxf(z, 0.0f) + log1pf(__expf(-fabsf(z)));
}

// ---------- K1: split-K proj GEMM + As2 precompute (NO atomics) ----------
// grid (64 ksplits of 80, 4 btiles of 64), block 256 = 8 warps, 2 CTAs/SM.
// Warp w handles 24 consecutive outputs; lane handles batches lane, lane+32.
// Partials go to g_Part[ks][b][j] via STG.128.
#define K1_KC 80
#define K1_BT 64
#define K1_XWORDS 5332                 // (80+2)*65 = 5330, rounded to mult of 4
#define K1_SMEM ((K1_XWORDS + (K1_KC + 2) * NOUT) * 4)

__global__ __launch_bounds__(256, 2)
void k1_proj(const float* __restrict__ x,
             const float* __restrict__ Wd,
             const float* __restrict__ WB,
             const float* __restrict__ WC,
             const float* __restrict__ Alog) {
    extern __shared__ float sm[];
    float* Xst = sm;                   // [k][b] (80+2) x 65
    float* Ws  = sm + K1_XWORDS;       // [k][j] (80+2) x 192, 16B aligned

    const int t    = threadIdx.x;
    const int cta  = blockIdx.y * gridDim.x + blockIdx.x;  // 0..255
    const int k0   = blockIdx.x * K1_KC;
    const int b0   = blockIdx.y * K1_BT;

    // As2 precompute: 256 CTAs x 320 elems (80 float4)
    if (t < 80) {
        int idx = cta * 320 + t * 4;
        float4 a = *(const float4*)&Alog[idx];
        const float c = -1.44269504088896f;
        float4 r;
        r.x = c * __expf(a.x); r.y = c * __expf(a.y);
        r.z = c * __expf(a.z); r.w = c * __expf(a.w);
        *(float4*)&g_As2[idx] = r;
    }

    // load X transposed: 64 rows x 20 quads
    for (int e = t; e < K1_BT * (K1_KC / 4); e += 256) {
        int row = e / 20;
        int q   = e - row * 20;
        float4 v = *(const float4*)&x[(b0 + row) * DIN + k0 + q * 4];
        int base = (q * 4) * 65 + row;
        Xst[base]       = v.x;
        Xst[base + 65]  = v.y;
        Xst[base + 130] = v.z;
        Xst[base + 195] = v.w;
    }
    // load W concatenated: 80 rows x 48 quads
    for (int e = t; e < K1_KC * 48; e += 256) {
        int k  = e / 48;
        int j4 = (e - k * 48) * 4;
        int kk = k0 + k;
        float4 v;
        if (j4 < RNK)      v = *(const float4*)&Wd[kk * RNK + j4];
        else if (j4 < 176) v = *(const float4*)&WB[kk * NST + (j4 - 160)];
        else               v = *(const float4*)&WC[kk * NST + (j4 - 176)];
        *(float4*)&Ws[k * NOUT + j4] = v;
    }
    __syncthreads();

    const int w    = t >> 5;
    const int lane = t & 31;
    const int jb   = w * 24;

    unsigned long long acc[2][12];
#pragma unroll
    for (int i = 0; i < 2; i++)
#pragma unroll
        for (int j = 0; j < 12; j++) acc[i][j] = 0ull;

    const float* wp = &Ws[jb];        // 96B-aligned
    const float* xp = &Xst[lane];

    ulonglong2 WA[6], WBr[6];
    float xaA, xbA, xaB, xbB;
#pragma unroll
    for (int i = 0; i < 6; i++) WA[i] = ((const ulonglong2*)wp)[i];
    xaA = xp[0]; xbA = xp[32];

#pragma unroll 1
    for (int k = 0; k < K1_KC; k += 2) {
        const float* wpn = wp + NOUT;
#pragma unroll
        for (int i = 0; i < 6; i++) WBr[i] = ((const ulonglong2*)wpn)[i];
        xaB = xp[65]; xbB = xp[97];
        {
            unsigned long long x2a = pack2(xaA, xaA);
            unsigned long long x2b = pack2(xbA, xbA);
#pragma unroll
            for (int i = 0; i < 6; i++) {
                ffma2(acc[0][2*i],   x2a, WA[i].x);
                ffma2(acc[0][2*i+1], x2a, WA[i].y);
                ffma2(acc[1][2*i],   x2b, WA[i].x);
                ffma2(acc[1][2*i+1], x2b, WA[i].y);
            }
        }
        wp += 2 * NOUT; xp += 130;
#pragma unroll
        for (int i = 0; i < 6; i++) WA[i] = ((const ulonglong2*)wp)[i];
        xaA = xp[0]; xbA = xp[32];
        {
            unsigned long long x2a = pack2(xaB, xaB);
            unsigned long long x2b = pack2(xbB, xbB);
#pragma unroll
            for (int i = 0; i < 6; i++) {
                ffma2(acc[0][2*i],   x2a, WBr[i].x);
                ffma2(acc[0][2*i+1], x2a, WBr[i].y);
                ffma2(acc[1][2*i],   x2b, WBr[i].x);
                ffma2(acc[1][2*i+1], x2b, WBr[i].y);
            }
        }
    }

    // epilogue: plain stores of partials, [ks][b][j] layout
    {
        float v0[24], v1[24];
#pragma unroll
        for (int j = 0; j < 12; j++) {
            unpack2(acc[0][j], v0[2*j], v0[2*j + 1]);
            unpack2(acc[1][j], v1[2*j], v1[2*j + 1]);
        }
        size_t base0 = ((size_t)blockIdx.x * BATCH + b0 + lane) * NOUT + jb;
        size_t base1 = base0 + (size_t)32 * NOUT;
#pragma unroll
        for (int p = 0; p < 6; p++) {
            *(float4*)&g_Part[base0 + p * 4] = *(float4*)&v0[p * 4];
            *(float4*)&g_Part[base1 + p * 4] = *(float4*)&v1[p * 4];
        }
    }
}

// ---------- K1R: reduce split-K partials -> g_Pt[j][b] ----------
// 48 CTAs x 256 threads; thread handles one (b, j4) float4, sums 64 partials.
__global__ __launch_bounds__(256)
void k1r_reduce() {
    int t  = blockIdx.x * 256 + threadIdx.x;   // 0..12287
    int b  = t / 48;
    int jq = t - b * 48;
    int j  = jq * 4;

    float4 s0 = {0,0,0,0}, s1 = {0,0,0,0}, s2 = {0,0,0,0}, s3 = {0,0,0,0};
    size_t base = (size_t)b * NOUT + j;
    const size_t stride = (size_t)BATCH * NOUT;
#pragma unroll 4
    for (int ks = 0; ks < KSPLIT; ks += 4) {
        float4 a0 = *(const float4*)&g_Part[base + (ks + 0) * stride];
        float4 a1 = *(const float4*)&g_Part[base + (ks + 1) * stride];
        float4 a2 = *(const float4*)&g_Part[base + (ks + 2) * stride];
        float4 a3 = *(const float4*)&g_Part[base + (ks + 3) * stride];
        s0.x += a0.x; s0.y += a0.y; s0.z += a0.z; s0.w += a0.w;
        s1.x += a1.x; s1.y += a1.y; s1.z += a1.z; s1.w += a1.w;
        s2.x += a2.x; s2.y += a2.y; s2.z += a2.z; s2.w += a2.w;
        s3.x += a3.x; s3.y += a3.y; s3.z += a3.z; s3.w += a3.w;
    }
    float r0 = (s0.x + s1.x) + (s2.x + s3.x);
    float r1 = (s0.y + s1.y) + (s2.y + s3.y);
    float r2 = (s0.z + s1.z) + (s2.z + s3.z);
    float r3 = (s0.w + s1.w) + (s2.w + s3.w);
    g_Pt[(j + 0) * BATCH + b] = r0;
    g_Pt[(j + 1) * BATCH + b] = r1;
    g_Pt[(j + 2) * BATCH + b] = r2;
    g_Pt[(j + 3) * BATCH + b] = r3;
}

// ---------- K2: dt = softplus(P_low @ W_dt + b_dt); also Ct + SBC ----------
// grid (40 d-blocks of 128, 8 btiles of 32), block 256, 3 CTAs/SM, one wave.
// Each CTA processes two 64-d chunks reusing the Ps tile.
#define K2B 32
#define K2_SMEM (((RNK + 1) * 64 + (RNK + 1) * K2B) * 4)

__global__ __launch_bounds__(256, 3)
void k2_dt(const float* __restrict__ Wdt,
           const float* __restrict__ bdt) {
    extern __shared__ float sm[];
    float* Wds = sm;                      // [r][dj] (160+1) x 64
    float* Ps  = sm + (RNK + 1) * 64;     // [r][bi] (160+1) x 32

    const int t  = threadIdx.x;
    const int b0 = blockIdx.y * K2B;
    const int tx = t & 15;   // dj group of 4
    const int ty = t >> 4;   // bi group of 2

    // load P tile once (160 x 32)
    for (int e = t; e < RNK * 8; e += 256) {
        int r = e >> 3, q = e & 7;
        *(float4*)&Ps[r * K2B + q * 4] = *(const float4*)&g_Pt[r * BATCH + b0 + q * 4];
    }

    for (int chunk = 0; chunk < 2; chunk++) {
        const int d0 = blockIdx.x * 128 + chunk * 64;
        __syncthreads();
        for (int e = t; e < RNK * 16; e += 256) {
            int r = e >> 4, q = e & 15;
            *(float4*)&Wds[r * 64 + q * 4] =
                *(const float4*)&Wdt[r * DIN + d0 + q * 4];
        }
        __syncthreads();

        unsigned long long acc[2][2];
        acc[0][0] = acc[0][1] = acc[1][0] = acc[1][1] = 0ull;

        const float* wrow = &Wds[tx * 4];
        const float* prow = &Ps[ty * 2];
        ulonglong2 WAr = *(const ulonglong2*)wrow;
        float2     PAr = *(const float2*)prow;

#pragma unroll 2
        for (int r = 0; r < RNK; r += 2) {
            ulonglong2 WBr = *(const ulonglong2*)(wrow + 64);
            float2     PBr = *(const float2*)(prow + K2B);
            {
                unsigned long long p0 = pack2(PAr.x, PAr.x);
                unsigned long long p1 = pack2(PAr.y, PAr.y);
                ffma2(acc[0][0], p0, WAr.x); ffma2(acc[0][1], p0, WAr.y);
                ffma2(acc[1][0], p1, WAr.x); ffma2(acc[1][1], p1, WAr.y);
            }
            wrow += 128; prow += 2 * K2B;
            WAr = *(const ulonglong2*)wrow;      // pad row safe at r=158
            PAr = *(const float2*)prow;
            {
                unsigned long long p0 = pack2(PBr.x, PBr.x);
                unsigned long long p1 = pack2(PBr.y, PBr.y);
                ffma2(acc[0][0], p0, WBr.x); ffma2(acc[0][1], p0, WBr.y);
                ffma2(acc[1][0], p1, WBr.x); ffma2(acc[1][1], p1, WBr.y);
            }
        }

        float4 bb = *(const float4*)&bdt[d0 + tx * 4];
#pragma unroll
        for (int i = 0; i < 2; i++) {
            float z0, z1, z2, z3;
            unpack2(acc[i][0], z0, z1);
            unpack2(acc[i][1], z2, z3);
            float4 dt4;
            dt4.x = softplus20(z0 + bb.x);
            dt4.y = softplus20(z1 + bb.y);
            dt4.z = softplus20(z2 + bb.z);
            dt4.w = softplus20(z3 + bb.w);
            *(float4*)&g_dt[(b0 + ty * 2 + i) * DIN + d0 + tx * 4] = dt4;
        }
    }

    // first d-block column materializes Ct and SBC for its b-tile
    if (blockIdx.x == 0) {
        for (int e = t; e < K2B * NST; e += 256) {
            int bi = e >> 4, n = e & 15;
            g_Ct[(b0 + bi) * NST + n] = g_Pt[(176 + n) * BATCH + b0 + bi];
        }
        if (t < K2B) {
            float s = 0.0f;
#pragma unroll
            for (int n = 0; n < NST; n++)
                s = fmaf(g_Pt[(160 + n) * BATCH + b0 + t],
                         g_Pt[(176 + n) * BATCH + b0 + t], s);
            g_SBC[b0 + t] = s;
        }
    }
}

// ---------- K3: stream h, produce y (warp-cooperative, 2-way ILP) ----------
// group = (b, 8 consecutive d). 4 lanes per (b,d), lane q covers n = q*4..q*4+3.
// grid 640 * 8 warps = 5120 warps; 163840 groups / 5120 = 32 = 16 double-iters.
#define NGRP (BATCH * DIN / 8)   // 163840
#define K3_GRID 640

__global__ __launch_bounds__(256, 5)
void k3_stream(const float* __restrict__ h,
               const float* __restrict__ x,
               const float* __restrict__ Dv,
               float* __restrict__ out) {
    const int t     = threadIdx.x;
    const int lane  = t & 31;
    const int p     = lane >> 2;
    const int q     = lane & 3;
    const int wglob = blockIdx.x * 8 + (t >> 5);
    const int nw    = K3_GRID * 8;           // 5120

#pragma unroll 1
    for (int g = wglob; g < NGRP; g += 2 * nw) {
        const int g2 = g + nw;               // always < NGRP (32 | NGRP/nw)
        int ba = g / 640,  ca = g - ba * 640,  da = ca * 8 + p;
        int bb = g2 / 640, cb = g2 - bb * 640, db = cb * 8 + p;

        float4 hva = __ldcs((const float4*)&h[((size_t)ba * DIN + da) * NST + q * 4]);
        float4 hvb = __ldcs((const float4*)&h[((size_t)bb * DIN + db) * NST + q * 4]);
        float  dta = g_dt[ba * DIN + da];
        float  dtb = g_dt[bb * DIN + db];
        float4 aa  = *(const float4*)&g_As2[da * NST + q * 4];
        float4 ab  = *(const float4*)&g_As2[db * NST + q * 4];
        float4 cca = *(const float4*)&g_Ct[ba * NST + q * 4];
        float4 ccb = *(const float4*)&g_Ct[bb * NST + q * 4];

        float sa = cca.x * (ex2f(dta * aa.x) * hva.x);
        sa = fmaf(cca.y, ex2f(dta * aa.y) * hva.y, sa);
        sa = fmaf(cca.z, ex2f(dta * aa.z) * hva.z, sa);
        sa = fmaf(cca.w, ex2f(dta * aa.w) * hva.w, sa);

        float sb = ccb.x * (ex2f(dtb * ab.x) * hvb.x);
        sb = fmaf(ccb.y, ex2f(dtb * ab.y) * hvb.y, sb);
        sb = fmaf(ccb.z, ex2f(dtb * ab.z) * hvb.z, sb);
        sb = fmaf(ccb.w, ex2f(dtb * ab.w) * hvb.w, sb);

        sa += __shfl_xor_sync(0xffffffffu, sa, 1);
        sa += __shfl_xor_sync(0xffffffffu, sa, 2);
        sb += __shfl_xor_sync(0xffffffffu, sb, 1);
        sb += __shfl_xor_sync(0xffffffffu, sb, 2);

        if (q == 0) {
            float xa = x[ba * DIN + da];
            float xb = x[bb * DIN + db];
            out[ba * DIN + da] = sa + xa * fmaf(dta, g_SBC[ba], Dv[da]);
            out[bb * DIN + db] = sb + xb * fmaf(dtb, g_SBC[bb], Dv[db]);
        }
    }
}

// ---------- launch ----------
extern "C" void kernel_launch(void* const* d_in, const int* in_sizes, int n_in,
                              void* d_out, int out_size) {
    const float* x    = (const float*)d_in[0];
    const float* h    = (const float*)d_in[1];
    const float* Wd   = (const float*)d_in[2];
    const float* Wdt  = (const float*)d_in[3];
    const float* bdt  = (const float*)d_in[4];
    const float* Alog = (const float*)d_in[5];
    const float* WB   = (const float*)d_in[6];
    const float* WC   = (const float*)d_in[7];
    const float* Dv   = (const float*)d_in[8];
    float* out = (float*)d_out;

    cudaFuncSetAttribute(k1_proj, cudaFuncAttributeMaxDynamicSharedMemorySize, K1_SMEM);
    cudaFuncSetAttribute(k2_dt,   cudaFuncAttributeMaxDynamicSharedMemorySize, K2_SMEM);

    k1_proj<<<dim3(DIN / K1_KC, BATCH / K1_BT), 256, K1_SMEM>>>(x, Wd, WB, WC, Alog);
    k1r_reduce<<<48, 256>>>();
    k2_dt<<<dim3(DIN / 128, BATCH / K2B), 256, K2_SMEM>>>(Wdt, bdt);
    k3_stream<<<K3_GRID, 256>>>(h, x, Dv, out);
}